// round 14
// baseline (speedup 1.0000x reference)
#include <cuda_runtime.h>
#include <cuda_fp16.h>
#include <cstdint>

#define N_NODES 50000
#define N_EDGES 800000
#define DIM 128
#define LN_EPS 1e-5f
#define SCAN_B 196          // ceil(50000/256)
#define WTILE 16384         // floats per 128x128 weight

// ---------------- scratch: __device__ globals, device-side references only --
// g_deg invariant: ZERO at entry of every kernel_launch execution.
// (zero-initialized at module load; k_fill re-zeroes it at the end of each run)
__device__ int    g_is64;
__device__ int    g_deg[N_NODES];
__device__ int    g_rowptr[N_NODES + 1];
__device__ int    g_cursor[N_NODES];
__device__ int    g_colsrc[N_EDGES];
__device__ int    g_bsum[256];
__device__ float4 g_X4[(size_t)N_NODES * 32];      // tf32-rounded input x
__device__ float4 g_W4[4 * WTILE / 4];             // tf32-rounded weights
__device__ __half g_P16[(size_t)N_NODES * DIM];    // mean branch (pre-agg), fp16
__device__ float4 g_Q4[(size_t)N_NODES * 32];      // self branch, fp32
__device__ float4 g_h14[(size_t)N_NODES * 32];     // layer-1 out (tf32-rounded)

__device__ __forceinline__ float to_tf32(float v) {
    uint32_t u;
    asm("cvt.rna.tf32.f32 %0, %1;" : "=r"(u) : "f"(v));
    return __uint_as_float(u);
}

// ---------------- fused setup + hist ----------------------------------------
// tf32 pre-round x & weights; per-block dtype probe; edge histogram.
// g_deg is already zero on entry (see invariant above).
__global__ void k_setup(const float* __restrict__ x,
                        const float* __restrict__ W1l, const float* __restrict__ W1r,
                        const float* __restrict__ W2l, const float* __restrict__ W2r,
                        const void* __restrict__ ei) {
    __shared__ int sm_is64;
    int tid = threadIdx.x;
    int i = blockIdx.x * blockDim.x + tid;

    if (tid == 0) {
        const int* e32 = (const int*)ei;
        int az = 1;
        for (int k = 0; k < 64; k++)
            if (e32[2 * k + 1] != 0) { az = 0; break; }
        sm_is64 = az;
        if (blockIdx.x == 0) g_is64 = az;   // for k_fill later
    }

    if (i < N_NODES * DIM) ((float*)g_X4)[i] = to_tf32(x[i]);
    if (i < WTILE) {
        float* W = (float*)g_W4;
        W[i]             = to_tf32(W1l[i]);
        W[WTILE + i]     = to_tf32(W1r[i]);
        W[2 * WTILE + i] = to_tf32(W2l[i]);
        W[3 * WTILE + i] = to_tf32(W2r[i]);
    }

    __syncthreads();
    if (i < N_EDGES) {
        int d = sm_is64 ? (int)((const long long*)ei)[N_EDGES + i]
                        : ((const int*)ei)[N_EDGES + i];
        if (d >= 0 && d < N_NODES) atomicAdd(&g_deg[d], 1);
    }
}

__device__ __forceinline__ int edge_at(const void* __restrict__ ei, int pos) {
    if (g_is64) return (int)((const long long*)ei)[pos];
    return ((const int*)ei)[pos];
}

// ---------------- CSR scans ----------------
__global__ void k_scan1() {                       // grid=196: per-block sums
    __shared__ int sm[256];
    int t = threadIdx.x;
    int i = blockIdx.x * 256 + t;
    sm[t] = (i < N_NODES) ? g_deg[i] : 0;
    __syncthreads();
#pragma unroll
    for (int off = 128; off > 0; off >>= 1) {
        if (t < off) sm[t] += sm[t + off];
        __syncthreads();
    }
    if (t == 0) g_bsum[blockIdx.x] = sm[0];
}

// merged scan: each block redundantly scans block sums, then local scan.
__global__ void k_scan3() {                       // grid=196
    __shared__ int smb[256];
    __shared__ int sml[256];
    int t = threadIdx.x;
    int bv = (t < SCAN_B) ? g_bsum[t] : 0;
    smb[t] = bv;
    __syncthreads();
#pragma unroll
    for (int off = 1; off < 256; off <<= 1) {
        int u = (t >= off) ? smb[t - off] : 0;
        __syncthreads();
        smb[t] += u;
        __syncthreads();
    }
    int block_off = (blockIdx.x == 0) ? 0 : smb[blockIdx.x - 1];
    int i = blockIdx.x * 256 + t;
    int v = (i < N_NODES) ? g_deg[i] : 0;
    sml[t] = v;
    __syncthreads();
#pragma unroll
    for (int off = 1; off < 256; off <<= 1) {
        int u = (t >= off) ? sml[t - off] : 0;
        __syncthreads();
        sml[t] += u;
        __syncthreads();
    }
    int excl = sml[t] - v + block_off;
    if (i < N_NODES) { g_rowptr[i] = excl; g_cursor[i] = excl; }
    if (i == N_NODES - 1) g_rowptr[N_NODES] = excl + v;
}

// fill colsrc; also re-zero g_deg for the next replay (scans are done with it)
__global__ void k_fill(const void* __restrict__ ei) {
    int e = blockIdx.x * blockDim.x + threadIdx.x;
    if (e < N_NODES) g_deg[e] = 0;                // restore invariant
    if (e < N_EDGES) {
        int d = edge_at(ei, N_EDGES + e);
        if (d >= 0 && d < N_NODES) {
            int s = edge_at(ei, e);
            if (s < 0) s = 0;
            if (s >= N_NODES) s = N_NODES - 1;
            int pos = atomicAdd(&g_cursor[d], 1);
            g_colsrc[pos] = s;
        }
    }
}

// ---------------- merged tf32 GEMM: [P16 | Q] = A @ [Wp ; Wq]^T -------------
// Tile 128(M) x 256(N); 512 threads / 16 warps x (32M x 64N); occ 2.
// A streamed ONCE per layer; 2-stage cp.async; stride-36 smem (conflict-free).
__device__ __forceinline__ void mma_tf32(float c[4], const uint32_t a[4],
                                         const uint32_t b[2]) {
    asm volatile(
        "mma.sync.aligned.m16n8k8.row.col.f32.tf32.tf32.f32 "
        "{%0,%1,%2,%3}, {%4,%5,%6,%7}, {%8,%9}, {%0,%1,%2,%3};\n"
        : "+f"(c[0]), "+f"(c[1]), "+f"(c[2]), "+f"(c[3])
        : "r"(a[0]), "r"(a[1]), "r"(a[2]), "r"(a[3]),
          "r"(b[0]), "r"(b[1]));
}

__device__ __forceinline__ void cp_async16(float* smem_dst, const float* gsrc, bool valid) {
    uint32_t s = (uint32_t)__cvta_generic_to_shared(smem_dst);
    int sz = valid ? 16 : 0;
    asm volatile("cp.async.ca.shared.global [%0], [%1], 16, %2;\n"
                 :: "r"(s), "l"(gsrc), "r"(sz));
}
#define CP_COMMIT() asm volatile("cp.async.commit_group;\n")
#define CP_WAIT1()  asm volatile("cp.async.wait_group 1;\n")
#define CP_WAIT0()  asm volatile("cp.async.wait_group 0;\n")

#define SPAD 36
#define A_STG (128 * SPAD)                       // 4608 floats per A stage
#define B_STG (256 * SPAD)                       // 9216 floats per B stage
#define OFF_B (2 * A_STG)
#define GEMM_SMEM_BYTES ((2 * A_STG + 2 * B_STG) * 4)   // 110592 B

__global__ __launch_bounds__(512, 2) void k_gemm(int layer1, int wP, int wQ) {
    extern __shared__ float dynsm[];
    const float* A  = layer1 ? (const float*)g_X4 : (const float*)g_h14;
    const float* Wp = (const float*)g_W4 + (size_t)wP * WTILE;
    const float* Wq = (const float*)g_W4 + (size_t)wQ * WTILE;

    int tid = threadIdx.x;
    int r0 = blockIdx.x * 128;

    // A: 128x32 = 1024 float4 (2 iters); B: 256x32 = 2048 float4 (4 iters)
#define FILL_STAGE(stg, ka)                                                    \
    {                                                                          \
        float* Ab = dynsm + (stg) * A_STG;                                     \
        float* Bb = dynsm + OFF_B + (stg) * B_STG;                             \
        _Pragma("unroll")                                                      \
        for (int i = 0; i < 2; i++) {                                          \
            int linear = i * 512 + tid;                                        \
            int m = linear >> 3;                                               \
            int kv = (linear & 7) * 4;                                         \
            int row = r0 + m;                                                  \
            cp_async16(&Ab[m * SPAD + kv],                                     \
                       A + (size_t)row * DIM + (ka) + kv, row < N_NODES);      \
        }                                                                      \
        _Pragma("unroll")                                                      \
        for (int i = 0; i < 4; i++) {                                          \
            int linear = i * 512 + tid;                                        \
            int n = linear >> 3;                                               \
            int kv = (linear & 7) * 4;                                         \
            const float* src = (n < 128) ? (Wp + n * DIM + (ka) + kv)          \
                                         : (Wq + (n - 128) * DIM + (ka) + kv); \
            cp_async16(&Bb[n * SPAD + kv], src, true);                         \
        }                                                                      \
        CP_COMMIT();                                                           \
    }

    FILL_STAGE(0, 0)

    int wid = tid >> 5, lane = tid & 31;
    int g = lane >> 2, tg = lane & 3;
    int warp_m = (wid >> 2) * 32;        // 4 m-groups
    int warp_n = (wid & 3) * 64;         // 4 n-groups over 256 cols

    float acc[2][8][4];
#pragma unroll
    for (int mt = 0; mt < 2; mt++)
#pragma unroll
        for (int nt = 0; nt < 8; nt++)
#pragma unroll
            for (int q = 0; q < 4; q++) acc[mt][nt][q] = 0.f;

#pragma unroll 1
    for (int kt = 0; kt < 4; kt++) {
        if (kt < 3) {
            FILL_STAGE((kt + 1) & 1, (kt + 1) * 32)
            CP_WAIT1();
        } else {
            CP_WAIT0();
        }
        __syncthreads();

        const float* Ab = dynsm + (kt & 1) * A_STG;
        const float* Bb = dynsm + OFF_B + (kt & 1) * B_STG;
#pragma unroll
        for (int ks = 0; ks < 32; ks += 8) {
            int kc = ks + tg;
            uint32_t afr[2][4];
#pragma unroll
            for (int mt = 0; mt < 2; mt++) {
                const float* Ar = Ab + (warp_m + mt * 16 + g) * SPAD;
                afr[mt][0] = __float_as_uint(Ar[kc]);
                afr[mt][1] = __float_as_uint(Ar[8 * SPAD + kc]);
                afr[mt][2] = __float_as_uint(Ar[kc + 4]);
                afr[mt][3] = __float_as_uint(Ar[8 * SPAD + kc + 4]);
            }
#pragma unroll
            for (int nt = 0; nt < 8; nt++) {
                const float* Br = Bb + (warp_n + nt * 8 + g) * SPAD;
                uint32_t bfr[2] = { __float_as_uint(Br[kc]),
                                    __float_as_uint(Br[kc + 4]) };
                mma_tf32(acc[0][nt], afr[0], bfr);
                mma_tf32(acc[1][nt], afr[1], bfr);
            }
        }
        __syncthreads();
    }

    // epilogue: cols < 128 -> P16 (fp16); cols >= 128 -> Q (fp32)
    float* Q = (float*)g_Q4;
#pragma unroll
    for (int mt = 0; mt < 2; mt++) {
        int row0 = r0 + warp_m + mt * 16 + g;
#pragma unroll
        for (int nt = 0; nt < 8; nt++) {
            int col = warp_n + nt * 8 + tg * 2;
            if (col < 128) {
                if (row0 < N_NODES)
                    *(__half2*)(g_P16 + (size_t)row0 * DIM + col) =
                        __floats2half2_rn(acc[mt][nt][0], acc[mt][nt][1]);
                if (row0 + 8 < N_NODES)
                    *(__half2*)(g_P16 + (size_t)(row0 + 8) * DIM + col) =
                        __floats2half2_rn(acc[mt][nt][2], acc[mt][nt][3]);
            } else {
                int cq = col - 128;
                if (row0 < N_NODES)
                    *(float2*)(Q + (size_t)row0 * DIM + cq) =
                        make_float2(acc[mt][nt][0], acc[mt][nt][1]);
                if (row0 + 8 < N_NODES)
                    *(float2*)(Q + (size_t)(row0 + 8) * DIM + cq) =
                        make_float2(acc[mt][nt][2], acc[mt][nt][3]);
            }
        }
    }
}

// ---------------- combine: out = [LN]( relu( mean_gather(P16) + Q + bias ) ) -
#define GATHER1(sidx)                                                          \
    {                                                                          \
        uint2 u = *(const uint2*)(g_P16 + (size_t)(sidx) * DIM + lane * 4);    \
        float2 fa = __half22float2(*(__half2*)&u.x);                           \
        float2 fb = __half22float2(*(__half2*)&u.y);                           \
        ax += fa.x; ay += fa.y; az += fb.x; aw += fb.y;                        \
    }

__global__ void k_combine(const float* __restrict__ bias,
                          const float* __restrict__ lnw,
                          const float* __restrict__ lnb,
                          float* __restrict__ out_ext, int do_ln)
{
    int w = (blockIdx.x * blockDim.x + threadIdx.x) >> 5;
    int lane = threadIdx.x & 31;
    if (w >= N_NODES) return;
    int beg = g_rowptr[w];
    int end = g_rowptr[w + 1];

    float ax = 0.f, ay = 0.f, az = 0.f, aw = 0.f;
    for (int base = beg; base < end; base += 32) {
        int rem = end - base;
        if (rem > 32) rem = 32;
        int idx = g_colsrc[base + (lane < rem ? lane : 0)];
        int j = 0;
        for (; j + 8 <= rem; j += 8) {
            int s0 = __shfl_sync(0xFFFFFFFFu, idx, j);
            int s1 = __shfl_sync(0xFFFFFFFFu, idx, j + 1);
            int s2 = __shfl_sync(0xFFFFFFFFu, idx, j + 2);
            int s3 = __shfl_sync(0xFFFFFFFFu, idx, j + 3);
            int s4 = __shfl_sync(0xFFFFFFFFu, idx, j + 4);
            int s5 = __shfl_sync(0xFFFFFFFFu, idx, j + 5);
            int s6 = __shfl_sync(0xFFFFFFFFu, idx, j + 6);
            int s7 = __shfl_sync(0xFFFFFFFFu, idx, j + 7);
            GATHER1(s0) GATHER1(s1) GATHER1(s2) GATHER1(s3)
            GATHER1(s4) GATHER1(s5) GATHER1(s6) GATHER1(s7)
        }
        for (; j < rem; j++) {
            int s = __shfl_sync(0xFFFFFFFFu, idx, j);
            GATHER1(s)
        }
    }
    int cnt = end - beg;
    float inv = 1.f / (float)(cnt > 0 ? cnt : 1);

    float4 q = g_Q4[(size_t)w * 32 + lane];
    float4 b4 = ((const float4*)bias)[lane];
    float vx = fmaxf(ax * inv + q.x + b4.x, 0.f);
    float vy = fmaxf(ay * inv + q.y + b4.y, 0.f);
    float vz = fmaxf(az * inv + q.z + b4.z, 0.f);
    float vw = fmaxf(aw * inv + q.w + b4.w, 0.f);

    if (!do_ln) {
        g_h14[(size_t)w * 32 + lane] =
            make_float4(to_tf32(vx), to_tf32(vy), to_tf32(vz), to_tf32(vw));
        return;
    }
    float s = (vx + vy) + (vz + vw);
#pragma unroll
    for (int off = 16; off > 0; off >>= 1)
        s += __shfl_xor_sync(0xFFFFFFFFu, s, off);
    float mu = s * (1.f / 128.f);
    float dx = vx - mu, dy = vy - mu, dz = vz - mu, dw = vw - mu;
    float sq = (dx * dx + dy * dy) + (dz * dz + dw * dw);
#pragma unroll
    for (int off = 16; off > 0; off >>= 1)
        sq += __shfl_xor_sync(0xFFFFFFFFu, sq, off);
    float rs = rsqrtf(sq * (1.f / 128.f) + LN_EPS);
    float4 wv = ((const float4*)lnw)[lane];
    float4 bv = ((const float4*)lnb)[lane];
    float4 o;
    o.x = dx * rs * wv.x + bv.x;
    o.y = dy * rs * wv.y + bv.y;
    o.z = dz * rs * wv.z + bv.z;
    o.w = dw * rs * wv.w + bv.w;
    ((float4*)out_ext)[(size_t)w * 32 + lane] = o;
}

// ---------------- launch: single stream, 8 kernels, no host objects ---------
extern "C" void kernel_launch(void* const* d_in, const int* in_sizes, int n_in,
                              void* d_out, int out_size) {
    const float* x   = (const float*)d_in[0];
    const void*  ei  = d_in[1];
    const float* W1l = (const float*)d_in[2];
    const float* b1l = (const float*)d_in[3];
    const float* W1r = (const float*)d_in[4];
    const float* W2l = (const float*)d_in[5];
    const float* b2l = (const float*)d_in[6];
    const float* W2r = (const float*)d_in[7];
    const float* lnw = (const float*)d_in[8];
    const float* lnb = (const float*)d_in[9];
    float* out = (float*)d_out;

    const int TB = 256;
    int gridS  = (N_NODES * DIM + TB - 1) / TB;  // 25000 (covers edges too)
    int gridE  = (N_EDGES + TB - 1) / TB;
    int gridWN = (N_NODES * 32 + TB - 1) / TB;
    int gridG  = (N_NODES + 127) / 128;          // 391

    cudaFuncSetAttribute(k_gemm, cudaFuncAttributeMaxDynamicSharedMemorySize,
                         GEMM_SMEM_BYTES);

    // fused setup+hist (g_deg zero on entry by invariant), then scans + fill
    k_setup<<<gridS, TB>>>(x, W1l, W1r, W2l, W2r, ei);
    k_scan1<<<SCAN_B, 256>>>();
    k_scan3<<<SCAN_B, 256>>>();
    k_fill<<<gridE, TB>>>(ei);

    // layer 1: merged GEMM (P16 = x@W1l^T, Q = x@W1r^T), then combine
    k_gemm<<<gridG, 512, GEMM_SMEM_BYTES>>>(1, 0, 1);
    k_combine<<<gridWN, TB>>>(b1l, lnw, lnb, out, 0);   // -> g_h14

    // layer 2
    k_gemm<<<gridG, 512, GEMM_SMEM_BYTES>>>(0, 2, 3);
    k_combine<<<gridWN, TB>>>(b2l, lnw, lnb, out, 1);   // + LN -> out
}

// round 17
// speedup vs baseline: 1.6770x; 1.6770x over previous
#include <cuda_runtime.h>
#include <cuda_fp16.h>
#include <cstdint>

#define N_NODES 50000
#define N_EDGES 800000
#define DIM 128
#define LN_EPS 1e-5f
#define SCAN_B 196          // ceil(50000/256)
#define WTILE 16384         // floats per 128x128 weight

// ---------------- scratch: __device__ globals, device-side references only --
// g_deg invariant: ZERO at entry of every kernel_launch execution.
// (zero-initialized at module load; k_fill re-zeroes it at the end of each run)
__device__ int    g_is64;
__device__ int    g_deg[N_NODES];
__device__ int    g_rowptr[N_NODES + 1];
__device__ int    g_cursor[N_NODES];
__device__ int    g_colsrc[N_EDGES];
__device__ int    g_bsum[256];
__device__ float4 g_X4[(size_t)N_NODES * 32];      // tf32-rounded input x
__device__ float4 g_W4[4 * WTILE / 4];             // tf32-rounded weights
__device__ __half g_P16[(size_t)N_NODES * DIM];    // mean branch (pre-agg), fp16
__device__ float4 g_Q4[(size_t)N_NODES * 32];      // self branch, fp32
__device__ float4 g_h14[(size_t)N_NODES * 32];     // layer-1 out (tf32-rounded)

__device__ __forceinline__ float to_tf32(float v) {
    uint32_t u;
    asm("cvt.rna.tf32.f32 %0, %1;" : "=r"(u) : "f"(v));
    return __uint_as_float(u);
}

// ---------------- fused setup + hist ----------------------------------------
// tf32 pre-round x & weights; per-block dtype probe; edge histogram.
// g_deg is already zero on entry (invariant above).
__global__ void k_setup(const float* __restrict__ x,
                        const float* __restrict__ W1l, const float* __restrict__ W1r,
                        const float* __restrict__ W2l, const float* __restrict__ W2r,
                        const void* __restrict__ ei) {
    __shared__ int sm_is64;
    int tid = threadIdx.x;
    int i = blockIdx.x * blockDim.x + tid;

    if (tid == 0) {
        const int* e32 = (const int*)ei;
        int az = 1;
        for (int k = 0; k < 64; k++)
            if (e32[2 * k + 1] != 0) { az = 0; break; }
        sm_is64 = az;
        if (blockIdx.x == 0) g_is64 = az;   // for k_fill later
    }

    if (i < N_NODES * DIM) ((float*)g_X4)[i] = to_tf32(x[i]);
    if (i < WTILE) {
        float* W = (float*)g_W4;
        W[i]             = to_tf32(W1l[i]);
        W[WTILE + i]     = to_tf32(W1r[i]);
        W[2 * WTILE + i] = to_tf32(W2l[i]);
        W[3 * WTILE + i] = to_tf32(W2r[i]);
    }

    __syncthreads();
    if (i < N_EDGES) {
        int d = sm_is64 ? (int)((const long long*)ei)[N_EDGES + i]
                        : ((const int*)ei)[N_EDGES + i];
        if (d >= 0 && d < N_NODES) atomicAdd(&g_deg[d], 1);
    }
}

__device__ __forceinline__ int edge_at(const void* __restrict__ ei, int pos) {
    if (g_is64) return (int)((const long long*)ei)[pos];
    return ((const int*)ei)[pos];
}

// ---------------- CSR scans ----------------
__global__ void k_scan1() {                       // grid=196: per-block sums
    __shared__ int sm[256];
    int t = threadIdx.x;
    int i = blockIdx.x * 256 + t;
    sm[t] = (i < N_NODES) ? g_deg[i] : 0;
    __syncthreads();
#pragma unroll
    for (int off = 128; off > 0; off >>= 1) {
        if (t < off) sm[t] += sm[t + off];
        __syncthreads();
    }
    if (t == 0) g_bsum[blockIdx.x] = sm[0];
}

// merged scan: each block redundantly scans block sums, then local scan.
__global__ void k_scan3() {                       // grid=196
    __shared__ int smb[256];
    __shared__ int sml[256];
    int t = threadIdx.x;
    int bv = (t < SCAN_B) ? g_bsum[t] : 0;
    smb[t] = bv;
    __syncthreads();
#pragma unroll
    for (int off = 1; off < 256; off <<= 1) {
        int u = (t >= off) ? smb[t - off] : 0;
        __syncthreads();
        smb[t] += u;
        __syncthreads();
    }
    int block_off = (blockIdx.x == 0) ? 0 : smb[blockIdx.x - 1];
    int i = blockIdx.x * 256 + t;
    int v = (i < N_NODES) ? g_deg[i] : 0;
    sml[t] = v;
    __syncthreads();
#pragma unroll
    for (int off = 1; off < 256; off <<= 1) {
        int u = (t >= off) ? sml[t - off] : 0;
        __syncthreads();
        sml[t] += u;
        __syncthreads();
    }
    int excl = sml[t] - v + block_off;
    if (i < N_NODES) { g_rowptr[i] = excl; g_cursor[i] = excl; }
    if (i == N_NODES - 1) g_rowptr[N_NODES] = excl + v;
}

// fill colsrc; also re-zero g_deg for the next replay (scans are done with it)
__global__ void k_fill(const void* __restrict__ ei) {
    int e = blockIdx.x * blockDim.x + threadIdx.x;
    if (e < N_NODES) g_deg[e] = 0;                // restore invariant
    if (e < N_EDGES) {
        int d = edge_at(ei, N_EDGES + e);
        if (d >= 0 && d < N_NODES) {
            int s = edge_at(ei, e);
            if (s < 0) s = 0;
            if (s >= N_NODES) s = N_NODES - 1;
            int pos = atomicAdd(&g_cursor[d], 1);
            g_colsrc[pos] = s;
        }
    }
}

// ---------------- tf32 GEMM (R11 proven shape: 128x128 tile, 256 thr, occ2) -
// out = A @ W^T; A, W tf32-pre-rounded. 8 warps x (32x64); 2-stage cp.async;
// stride-36 smem (conflict-free for the fragment access pattern).
__device__ __forceinline__ void mma_tf32(float c[4], const uint32_t a[4],
                                         const uint32_t b[2]) {
    asm volatile(
        "mma.sync.aligned.m16n8k8.row.col.f32.tf32.tf32.f32 "
        "{%0,%1,%2,%3}, {%4,%5,%6,%7}, {%8,%9}, {%0,%1,%2,%3};\n"
        : "+f"(c[0]), "+f"(c[1]), "+f"(c[2]), "+f"(c[3])
        : "r"(a[0]), "r"(a[1]), "r"(a[2]), "r"(a[3]),
          "r"(b[0]), "r"(b[1]));
}

__device__ __forceinline__ void cp_async16(float* smem_dst, const float* gsrc, bool valid) {
    uint32_t s = (uint32_t)__cvta_generic_to_shared(smem_dst);
    int sz = valid ? 16 : 0;
    asm volatile("cp.async.ca.shared.global [%0], [%1], 16, %2;\n"
                 :: "r"(s), "l"(gsrc), "r"(sz));
}
#define CP_COMMIT() asm volatile("cp.async.commit_group;\n")
#define CP_WAIT1()  asm volatile("cp.async.wait_group 1;\n")
#define CP_WAIT0()  asm volatile("cp.async.wait_group 0;\n")

#define SPAD 36
#define STG_F (128 * SPAD)                       // floats per (A or B) stage
#define GEMM_SMEM_BYTES (4 * STG_F * 4)          // A0,A1,B0,B1 = 73728 B

__global__ __launch_bounds__(256, 2) void k_gemm(int layer1, int widx, int out_fp16) {
    extern __shared__ float dynsm[];
    const float* A = layer1 ? (const float*)g_X4 : (const float*)g_h14;
    const float* W = (const float*)g_W4 + (size_t)widx * WTILE;

    int tid = threadIdx.x;
    int r0 = blockIdx.x * 128;

#define FILL_STAGE(stg, ka)                                                    \
    {                                                                          \
        float* Ab = dynsm + (stg) * STG_F;                                     \
        float* Bb = dynsm + 2 * STG_F + (stg) * STG_F;                         \
        _Pragma("unroll")                                                      \
        for (int i = 0; i < 4; i++) {                                          \
            int linear = i * 256 + tid;                                        \
            int m = linear >> 3;                                               \
            int kv = (linear & 7) * 4;                                         \
            int row = r0 + m;                                                  \
            cp_async16(&Ab[m * SPAD + kv],                                     \
                       A + (size_t)row * DIM + (ka) + kv, row < N_NODES);      \
            cp_async16(&Bb[m * SPAD + kv],                                     \
                       W + m * DIM + (ka) + kv, true);                         \
        }                                                                      \
        CP_COMMIT();                                                           \
    }

    FILL_STAGE(0, 0)

    int wid = tid >> 5, lane = tid & 31;
    int g = lane >> 2, tg = lane & 3;
    int warp_m = (wid >> 1) * 32;
    int warp_n = (wid & 1) * 64;

    float acc[2][8][4];
#pragma unroll
    for (int mt = 0; mt < 2; mt++)
#pragma unroll
        for (int nt = 0; nt < 8; nt++)
#pragma unroll
            for (int q = 0; q < 4; q++) acc[mt][nt][q] = 0.f;

#pragma unroll 1
    for (int kt = 0; kt < 4; kt++) {
        if (kt < 3) {
            FILL_STAGE((kt + 1) & 1, (kt + 1) * 32)
            CP_WAIT1();
        } else {
            CP_WAIT0();
        }
        __syncthreads();

        const float* Ab = dynsm + (kt & 1) * STG_F;
        const float* Bb = dynsm + 2 * STG_F + (kt & 1) * STG_F;
#pragma unroll
        for (int ks = 0; ks < 32; ks += 8) {
            int kc = ks + tg;
            uint32_t afr[2][4];
#pragma unroll
            for (int mt = 0; mt < 2; mt++) {
                const float* Ar = Ab + (warp_m + mt * 16 + g) * SPAD;
                afr[mt][0] = __float_as_uint(Ar[kc]);
                afr[mt][1] = __float_as_uint(Ar[8 * SPAD + kc]);
                afr[mt][2] = __float_as_uint(Ar[kc + 4]);
                afr[mt][3] = __float_as_uint(Ar[8 * SPAD + kc + 4]);
            }
#pragma unroll
            for (int nt = 0; nt < 8; nt++) {
                const float* Br = Bb + (warp_n + nt * 8 + g) * SPAD;
                uint32_t bfr[2] = { __float_as_uint(Br[kc]),
                                    __float_as_uint(Br[kc + 4]) };
                mma_tf32(acc[0][nt], afr[0], bfr);
                mma_tf32(acc[1][nt], afr[1], bfr);
            }
        }
        __syncthreads();
    }

    // epilogue: c0:(g,2tg) c1:(g,2tg+1) c2:(g+8,2tg) c3:(g+8,2tg+1)
    float* Q = (float*)g_Q4;
#pragma unroll
    for (int mt = 0; mt < 2; mt++) {
        int row0 = r0 + warp_m + mt * 16 + g;
#pragma unroll
        for (int nt = 0; nt < 8; nt++) {
            int col = warp_n + nt * 8 + tg * 2;
            if (out_fp16) {
                if (row0 < N_NODES)
                    *(__half2*)(g_P16 + (size_t)row0 * DIM + col) =
                        __floats2half2_rn(acc[mt][nt][0], acc[mt][nt][1]);
                if (row0 + 8 < N_NODES)
                    *(__half2*)(g_P16 + (size_t)(row0 + 8) * DIM + col) =
                        __floats2half2_rn(acc[mt][nt][2], acc[mt][nt][3]);
            } else {
                if (row0 < N_NODES)
                    *(float2*)(Q + (size_t)row0 * DIM + col) =
                        make_float2(acc[mt][nt][0], acc[mt][nt][1]);
                if (row0 + 8 < N_NODES)
                    *(float2*)(Q + (size_t)(row0 + 8) * DIM + col) =
                        make_float2(acc[mt][nt][2], acc[mt][nt][3]);
            }
        }
    }
}

// ---------------- combine: out = [LN]( relu( mean_gather(P16) + Q + bias ) ) -
#define GATHER1(sidx)                                                          \
    {                                                                          \
        uint2 u = *(const uint2*)(g_P16 + (size_t)(sidx) * DIM + lane * 4);    \
        float2 fa = __half22float2(*(__half2*)&u.x);                           \
        float2 fb = __half22float2(*(__half2*)&u.y);                           \
        ax += fa.x; ay += fa.y; az += fb.x; aw += fb.y;                        \
    }

__global__ void k_combine(const float* __restrict__ bias,
                          const float* __restrict__ lnw,
                          const float* __restrict__ lnb,
                          float* __restrict__ out_ext, int do_ln)
{
    int w = (blockIdx.x * blockDim.x + threadIdx.x) >> 5;
    int lane = threadIdx.x & 31;
    if (w >= N_NODES) return;
    int beg = g_rowptr[w];
    int end = g_rowptr[w + 1];

    float ax = 0.f, ay = 0.f, az = 0.f, aw = 0.f;
    for (int base = beg; base < end; base += 32) {
        int rem = end - base;
        if (rem > 32) rem = 32;
        int idx = g_colsrc[base + (lane < rem ? lane : 0)];
        int j = 0;
        for (; j + 8 <= rem; j += 8) {
            int s0 = __shfl_sync(0xFFFFFFFFu, idx, j);
            int s1 = __shfl_sync(0xFFFFFFFFu, idx, j + 1);
            int s2 = __shfl_sync(0xFFFFFFFFu, idx, j + 2);
            int s3 = __shfl_sync(0xFFFFFFFFu, idx, j + 3);
            int s4 = __shfl_sync(0xFFFFFFFFu, idx, j + 4);
            int s5 = __shfl_sync(0xFFFFFFFFu, idx, j + 5);
            int s6 = __shfl_sync(0xFFFFFFFFu, idx, j + 6);
            int s7 = __shfl_sync(0xFFFFFFFFu, idx, j + 7);
            GATHER1(s0) GATHER1(s1) GATHER1(s2) GATHER1(s3)
            GATHER1(s4) GATHER1(s5) GATHER1(s6) GATHER1(s7)
        }
        for (; j < rem; j++) {
            int s = __shfl_sync(0xFFFFFFFFu, idx, j);
            GATHER1(s)
        }
    }
    int cnt = end - beg;
    float inv = 1.f / (float)(cnt > 0 ? cnt : 1);

    float4 q = g_Q4[(size_t)w * 32 + lane];
    float4 b4 = ((const float4*)bias)[lane];
    float vx = fmaxf(ax * inv + q.x + b4.x, 0.f);
    float vy = fmaxf(ay * inv + q.y + b4.y, 0.f);
    float vz = fmaxf(az * inv + q.z + b4.z, 0.f);
    float vw = fmaxf(aw * inv + q.w + b4.w, 0.f);

    if (!do_ln) {
        g_h14[(size_t)w * 32 + lane] =
            make_float4(to_tf32(vx), to_tf32(vy), to_tf32(vz), to_tf32(vw));
        return;
    }
    float s = (vx + vy) + (vz + vw);
#pragma unroll
    for (int off = 16; off > 0; off >>= 1)
        s += __shfl_xor_sync(0xFFFFFFFFu, s, off);
    float mu = s * (1.f / 128.f);
    float dx = vx - mu, dy = vy - mu, dz = vz - mu, dw = vw - mu;
    float sq = (dx * dx + dy * dy) + (dz * dz + dw * dw);
#pragma unroll
    for (int off = 16; off > 0; off >>= 1)
        sq += __shfl_xor_sync(0xFFFFFFFFu, sq, off);
    float rs = rsqrtf(sq * (1.f / 128.f) + LN_EPS);
    float4 wv = ((const float4*)lnw)[lane];
    float4 bv = ((const float4*)lnb)[lane];
    float4 o;
    o.x = dx * rs * wv.x + bv.x;
    o.y = dy * rs * wv.y + bv.y;
    o.z = dz * rs * wv.z + bv.z;
    o.w = dw * rs * wv.w + bv.w;
    ((float4*)out_ext)[(size_t)w * 32 + lane] = o;
}

// ---------------- launch: single stream, 10 kernels, no host objects --------
extern "C" void kernel_launch(void* const* d_in, const int* in_sizes, int n_in,
                              void* d_out, int out_size) {
    const float* x   = (const float*)d_in[0];
    const void*  ei  = d_in[1];
    const float* W1l = (const float*)d_in[2];
    const float* b1l = (const float*)d_in[3];
    const float* W1r = (const float*)d_in[4];
    const float* W2l = (const float*)d_in[5];
    const float* b2l = (const float*)d_in[6];
    const float* W2r = (const float*)d_in[7];
    const float* lnw = (const float*)d_in[8];
    const float* lnb = (const float*)d_in[9];
    float* out = (float*)d_out;

    const int TB = 256;
    int gridS  = (N_NODES * DIM + TB - 1) / TB;  // 25000 (covers edges too)
    int gridE  = (N_EDGES + TB - 1) / TB;
    int gridWN = (N_NODES * 32 + TB - 1) / TB;
    int gridG  = (N_NODES + 127) / 128;          // 391

    cudaFuncSetAttribute(k_gemm, cudaFuncAttributeMaxDynamicSharedMemorySize,
                         GEMM_SMEM_BYTES);

    // fused setup+hist (g_deg zero on entry by invariant), then scans + fill
    k_setup<<<gridS, TB>>>(x, W1l, W1r, W2l, W2r, ei);
    k_scan1<<<SCAN_B, 256>>>();
    k_scan3<<<SCAN_B, 256>>>();
    k_fill<<<gridE, TB>>>(ei);

    // layer 1: P16 = x@W1l^T, Q = x@W1r^T ; combine -> g_h14
    k_gemm<<<gridG, TB, GEMM_SMEM_BYTES>>>(1, 0, 1);
    k_gemm<<<gridG, TB, GEMM_SMEM_BYTES>>>(1, 1, 0);
    k_combine<<<gridWN, TB>>>(b1l, lnw, lnb, out, 0);

    // layer 2: P16 = h1@W2l^T, Q = h1@W2r^T ; combine+LN -> out
    k_gemm<<<gridG, TB, GEMM_SMEM_BYTES>>>(0, 2, 1);
    k_gemm<<<gridG, TB, GEMM_SMEM_BYTES>>>(0, 3, 0);
    k_combine<<<gridWN, TB>>>(b2l, lnw, lnb, out, 1);
}